// round 6
// baseline (speedup 1.0000x reference)
#include <cuda_runtime.h>
#include <cuda_bf16.h>
#include <cstdint>

// Problem constants (fixed by setup_inputs)
#define BATCH 4
#define MDIM 4096
#define NDIM 32
#define CDIM 256
#define DDIM 128
#define ROWS (BATCH * MDIM)        // 16384
#define NCHUNK 8
#define ROWS_PER_CHUNK (ROWS / NCHUNK)      // 2048
#define BM_PER_CHUNK (ROWS_PER_CHUNK / 64)  // 32
#define LN_EPS 1e-5f
#define SCALE 0.08838834764831845f // 1/sqrt(128)

// ---------------- scratch (device globals, no allocation) ----------------
__device__ __align__(16) float g_Mraw[CDIM * CDIM]; // Wq @ Wk^T
__device__ __align__(16) float g_M2[CDIM * CDIM];   // Mraw[c][c'] * k_gamma[c']
__device__ __align__(16) float g_bv[CDIM];          // Wk[c',:]·bq
__device__ __align__(16) float g_bv2[CDIM];         // k_gamma * bv
__device__ __align__(16) float g_rowvec[CDIM];      // mb[c] + u[c]
__device__ float g_const[1];                        // cb + bb
__device__ float2 g_stat[ROWS];                     // {mu, rs} per row of x
__device__ __align__(16) float g_w[ROWS * CDIM];    // per-row weight vectors
__device__ float g_Bc[ROWS];                        // per-row scalar bias

// ---------------- helpers ----------------
__device__ __forceinline__ float blockSum256(float v, float* s8) {
    #pragma unroll
    for (int o = 16; o; o >>= 1) v += __shfl_xor_sync(0xffffffffu, v, o);
    __syncthreads();
    if ((threadIdx.x & 31) == 0) s8[threadIdx.x >> 5] = v;
    __syncthreads();
    float tot = 0.f;
    #pragma unroll
    for (int i = 0; i < 8; i++) tot += s8[i];
    return tot;
}

#define FMA2(d, a, b) \
    asm("fma.rn.f32x2 %0, %1, %2, %0;" : "+l"(d) : "l"(a), "l"(b))
#define PACK2(out, lo, hi) \
    asm("mov.b64 %0, {%1, %2};" : "=l"(out) : "r"(__float_as_uint(lo)), "r"(__float_as_uint(hi)))

__device__ __forceinline__ float2 unpack2(unsigned long long v) {
    unsigned int lo, hi;
    asm("mov.b64 {%0, %1}, %2;" : "=r"(lo), "=r"(hi) : "l"(v));
    return make_float2(__uint_as_float(lo), __uint_as_float(hi));
}

// ---------------- K1a: Mraw = Wq(256x128) @ Wk^T(128x256), tiled ----------------
__global__ void prepA_kernel(const float* __restrict__ Wq, const float* __restrict__ Wk) {
    __shared__ float As[32][68];
    __shared__ float Bs[32][68];
    const int bm = blockIdx.y * 64;
    const int bn = blockIdx.x * 64;
    const int tid = threadIdx.x;
    const int tx = tid & 15, ty = tid >> 4;
    const int r = tid >> 2, dq = tid & 3;

    float acc[4][4];
    #pragma unroll
    for (int i = 0; i < 4; i++)
        #pragma unroll
        for (int j = 0; j < 4; j++) acc[i][j] = 0.f;

    for (int k0 = 0; k0 < DDIM; k0 += 32) {
        float4 a0 = *(const float4*)(Wq + (size_t)(bm + r) * DDIM + k0 + dq * 8);
        float4 a1 = *(const float4*)(Wq + (size_t)(bm + r) * DDIM + k0 + dq * 8 + 4);
        float4 b0 = *(const float4*)(Wk + (size_t)(bn + r) * DDIM + k0 + dq * 8);
        float4 b1 = *(const float4*)(Wk + (size_t)(bn + r) * DDIM + k0 + dq * 8 + 4);
        As[dq * 8 + 0][r] = a0.x; As[dq * 8 + 1][r] = a0.y;
        As[dq * 8 + 2][r] = a0.z; As[dq * 8 + 3][r] = a0.w;
        As[dq * 8 + 4][r] = a1.x; As[dq * 8 + 5][r] = a1.y;
        As[dq * 8 + 6][r] = a1.z; As[dq * 8 + 7][r] = a1.w;
        Bs[dq * 8 + 0][r] = b0.x; Bs[dq * 8 + 1][r] = b0.y;
        Bs[dq * 8 + 2][r] = b0.z; Bs[dq * 8 + 3][r] = b0.w;
        Bs[dq * 8 + 4][r] = b1.x; Bs[dq * 8 + 5][r] = b1.y;
        Bs[dq * 8 + 6][r] = b1.z; Bs[dq * 8 + 7][r] = b1.w;
        __syncthreads();
        #pragma unroll
        for (int k = 0; k < 32; k++) {
            float4 a = *(const float4*)&As[k][ty * 4];
            float4 b = *(const float4*)&Bs[k][tx * 4];
            float ai[4] = {a.x, a.y, a.z, a.w};
            float bj[4] = {b.x, b.y, b.z, b.w};
            #pragma unroll
            for (int i = 0; i < 4; i++)
                #pragma unroll
                for (int j = 0; j < 4; j++) acc[i][j] += ai[i] * bj[j];
        }
        __syncthreads();
    }
    #pragma unroll
    for (int i = 0; i < 4; i++)
        *(float4*)(g_Mraw + (size_t)(bm + ty * 4 + i) * CDIM + bn + tx * 4) =
            make_float4(acc[i][0], acc[i][1], acc[i][2], acc[i][3]);
}

// ---------------- K1b: per-c derived vectors ----------------
__global__ void prepB_kernel(const float* __restrict__ Wq, const float* __restrict__ Wk,
                             const float* __restrict__ bq, const float* __restrict__ bk,
                             const float* __restrict__ kg, const float* __restrict__ kb) {
    const int c = blockIdx.x;
    const int t = threadIdx.x;
    __shared__ float s8[8];
    float mraw = g_Mraw[(size_t)c * CDIM + t];
    g_M2[(size_t)c * CDIM + t] = mraw * kg[t];
    float mb = blockSum256(mraw * kb[t], s8);
    float u  = blockSum256(t < DDIM ? Wq[(size_t)c * DDIM + t] * bk[t] : 0.f, s8);
    float bv = blockSum256(t < DDIM ? Wk[(size_t)c * DDIM + t] * bq[t] : 0.f, s8);
    if (t == 0) {
        g_rowvec[c] = mb + u;
        g_bv[c] = bv;
        g_bv2[c] = bv * kg[c];
    }
}

// ---------------- K1c: const scalar = cb + bb ----------------
__global__ void prep2_kernel(const float* __restrict__ bq, const float* __restrict__ bk,
                             const float* __restrict__ kb) {
    const int t = threadIdx.x;
    __shared__ float s8[8];
    float cb = blockSum256(g_bv[t] * kb[t], s8);
    float bb = blockSum256(t < DDIM ? bq[t] * bk[t] : 0.f, s8);
    if (t == 0) g_const[0] = cb + bb;
}

// ---------------- K2: per-row {mu, rs} of x (warp/row, 8 rows/block) ----------------
__global__ void __launch_bounds__(256)
stats_kernel(const float* __restrict__ x) {
    const int w = threadIdx.x >> 5, l = threadIdx.x & 31;
    const int row = blockIdx.x * 8 + w;
    const float* xr = x + (size_t)row * CDIM + l * 8;
    float4 xa = *(const float4*)(xr);
    float4 xb = *(const float4*)(xr + 4);
    float s1 = xa.x + xa.y + xa.z + xa.w + xb.x + xb.y + xb.z + xb.w;
    float s2 = xa.x*xa.x + xa.y*xa.y + xa.z*xa.z + xa.w*xa.w
             + xb.x*xb.x + xb.y*xb.y + xb.z*xb.z + xb.w*xb.w;
    #pragma unroll
    for (int o = 16; o; o >>= 1) {
        s1 += __shfl_xor_sync(0xffffffffu, s1, o);
        s2 += __shfl_xor_sync(0xffffffffu, s2, o);
    }
    if (l == 0) {
        float mu = s1 * (1.f / CDIM);
        float var = s2 * (1.f / CDIM) - mu * mu;
        g_stat[row] = make_float2(mu, rsqrtf(var + LN_EPS));
    }
}

// ---------------- K3: GEMM chunk  w = LN(x) @ M2 + bv2 ; also Bc ----------------
// 64(M) x 128(N) tile, BK=16, 256 threads, 4x8/thread, f32x2 FMAs, reg prefetch.
__global__ void __launch_bounds__(256)
gemm_kernel(const float* __restrict__ x, const float* __restrict__ qg,
            const float* __restrict__ qb, int bmBase) {
    __shared__ __align__(16) float As[16][68];
    __shared__ __align__(16) float Bs[16][132];

    const int bm = (bmBase + blockIdx.y) * 64;
    const int bn = blockIdx.x * 128;
    const int tid = threadIdx.x;
    const int tx = tid & 15;
    const int ty = tid >> 4;
    const int r0 = tid >> 2;
    const int aq = tid & 3;
    const int kr = tid >> 4;
    const int cq = tid & 15;

    const float2 st = g_stat[bm + r0];

    const float* xp  = x + (size_t)(bm + r0) * CDIM + aq * 4;
    const float* qgp = qg + aq * 4;
    const float* qbp = qb + aq * 4;
    const float* rvp = g_rowvec + aq * 4;
    const float* bpg = g_M2 + (size_t)kr * CDIM + bn + cq * 8;

    unsigned long long acc[4][4];
    #pragma unroll
    for (int i = 0; i < 4; i++)
        #pragma unroll
        for (int j = 0; j < 4; j++) acc[i][j] = 0ull;
    float bcacc = 0.f;

    float4 xa  = *(const float4*)(xp);
    float4 gq  = *(const float4*)(qgp);
    float4 gb  = *(const float4*)(qbp);
    float4 b0v = *(const float4*)(bpg);
    float4 b1v = *(const float4*)(bpg + 4);

    for (int k0 = 0; k0 < CDIM; k0 += 16) {
        // stage A with fused LayerNorm; accumulate Bc partial dot
        {
            float t0 = st.y * gq.x, t1 = st.y * gq.y, t2 = st.y * gq.z, t3 = st.y * gq.w;
            float l0 = fmaf(xa.x, t0, gb.x - st.x * t0);
            float l1 = fmaf(xa.y, t1, gb.y - st.x * t1);
            float l2 = fmaf(xa.z, t2, gb.z - st.x * t2);
            float l3 = fmaf(xa.w, t3, gb.w - st.x * t3);
            As[aq * 4 + 0][r0] = l0;
            As[aq * 4 + 1][r0] = l1;
            As[aq * 4 + 2][r0] = l2;
            As[aq * 4 + 3][r0] = l3;
            float4 rv = *(const float4*)(rvp + k0);
            bcacc += l0 * rv.x + l1 * rv.y + l2 * rv.z + l3 * rv.w;
        }
        *(float4*)&Bs[kr][cq * 8]     = b0v;
        *(float4*)&Bs[kr][cq * 8 + 4] = b1v;
        __syncthreads();

        if (k0 + 16 < CDIM) {
            xa  = *(const float4*)(xp + k0 + 16);
            gq  = *(const float4*)(qgp + k0 + 16);
            gb  = *(const float4*)(qbp + k0 + 16);
            b0v = *(const float4*)(bpg + (size_t)(k0 + 16) * CDIM);
            b1v = *(const float4*)(bpg + (size_t)(k0 + 16) * CDIM + 4);
        }

        #pragma unroll
        for (int k = 0; k < 16; k++) {
            float4 a = *(const float4*)&As[k][ty * 4];
            const unsigned long long* p0 = (const unsigned long long*)&Bs[k][tx * 4];
            const unsigned long long* p1 = (const unsigned long long*)&Bs[k][64 + tx * 4];
            unsigned long long b0 = p0[0], b1 = p0[1], b2 = p1[0], b3 = p1[1];
            float av[4] = {a.x, a.y, a.z, a.w};
            #pragma unroll
            for (int i = 0; i < 4; i++) {
                unsigned long long ad;
                PACK2(ad, av[i], av[i]);
                FMA2(acc[i][0], ad, b0);
                FMA2(acc[i][1], ad, b1);
                FMA2(acc[i][2], ad, b2);
                FMA2(acc[i][3], ad, b3);
            }
        }
        __syncthreads();
    }

    // Bc: reduce over the 4 aq-lanes (adjacent within warp, same r0)
    bcacc += __shfl_xor_sync(0xffffffffu, bcacc, 1);
    bcacc += __shfl_xor_sync(0xffffffffu, bcacc, 2);
    if (aq == 0 && blockIdx.x == 0)
        g_Bc[bm + r0] = bcacc + g_const[0];

    float4 bias0 = *(const float4*)(g_bv2 + bn + tx * 4);
    float4 bias1 = *(const float4*)(g_bv2 + bn + 64 + tx * 4);
    #pragma unroll
    for (int i = 0; i < 4; i++) {
        const int row = bm + ty * 4 + i;
        float2 p0 = unpack2(acc[i][0]);
        float2 p1 = unpack2(acc[i][1]);
        float2 p2 = unpack2(acc[i][2]);
        float2 p3 = unpack2(acc[i][3]);
        *(float4*)(g_w + (size_t)row * CDIM + bn + tx * 4) =
            make_float4(p0.x + bias0.x, p0.y + bias0.y, p1.x + bias0.z, p1.y + bias0.w);
        *(float4*)(g_w + (size_t)row * CDIM + bn + 64 + tx * 4) =
            make_float4(p2.x + bias1.x, p2.y + bias1.y, p3.x + bias1.z, p3.y + bias1.w);
    }
}

// ---------------- K4: attention chunk (stream y, softmax, z-sum) ----------------
__global__ void attn_kernel(const float* __restrict__ y, const float* __restrict__ z,
                            float* __restrict__ out, int rowBase) {
    const int row = rowBase + blockIdx.x;
    const int tid = threadIdx.x;
    __shared__ __align__(16) float sw[CDIM];
    __shared__ float s8[8];
    __shared__ float sdot[NDIM];

    float wv = g_w[(size_t)row * CDIM + tid];
    sw[tid] = wv;
    float G = blockSum256(wv, s8);   // includes syncthreads -> sw visible

    const int n = tid >> 3, t8 = tid & 7;
    const float* yr = y + ((size_t)row * NDIM + n) * CDIM;
    float S1 = 0.f, S2 = 0.f, S3 = 0.f;
    #pragma unroll
    for (int j = 0; j < 8; j++) {
        const int col = j * 32 + t8 * 4;
        float4 yv = __ldcs((const float4*)(yr + col));
        float4 w4 = *(const float4*)(sw + col);
        S1 += yv.x + yv.y + yv.z + yv.w;
        S2 += yv.x * yv.x + yv.y * yv.y + yv.z * yv.z + yv.w * yv.w;
        S3 += yv.x * w4.x + yv.y * w4.y + yv.z * w4.z + yv.w * w4.w;
    }
    #pragma unroll
    for (int o = 4; o; o >>= 1) {
        S1 += __shfl_down_sync(0xffffffffu, S1, o);
        S2 += __shfl_down_sync(0xffffffffu, S2, o);
        S3 += __shfl_down_sync(0xffffffffu, S3, o);
    }
    if (t8 == 0) {
        float mu = S1 * (1.f / CDIM);
        float var = S2 * (1.f / CDIM) - mu * mu;
        float rs = rsqrtf(var + LN_EPS);
        sdot[n] = SCALE * (rs * (S3 - mu * G) + g_Bc[row]);
    }
    __syncthreads();
    if (tid < NDIM) {
        float v = sdot[tid];
        float m = v;
        #pragma unroll
        for (int o = 16; o; o >>= 1) m = fmaxf(m, __shfl_xor_sync(0xffffffffu, m, o));
        float e = expf(v - m);
        float zb = z[(size_t)row * NDIM + tid];
        float se = e, sez = e * zb;
        #pragma unroll
        for (int o = 16; o; o >>= 1) {
            se += __shfl_xor_sync(0xffffffffu, se, o);
            sez += __shfl_xor_sync(0xffffffffu, sez, o);
        }
        if (tid == 0) out[row] = sez / se;
    }
}

// ---------------- launch: two-stream pipelined graph ----------------
// Streams/events are created once on the first (uncaptured) correctness call;
// every call then issues the IDENTICAL launch sequence (same work, same output).
static cudaStream_t g_s2 = nullptr;
static cudaEvent_t g_evRoot, g_evStats, g_evDone;
static cudaEvent_t g_evG[NCHUNK];

extern "C" void kernel_launch(void* const* d_in, const int* in_sizes, int n_in,
                              void* d_out, int out_size) {
    const float* x  = (const float*)d_in[0];
    const float* y  = (const float*)d_in[1];
    const float* z  = (const float*)d_in[2];
    const float* qg = (const float*)d_in[3];
    const float* qb = (const float*)d_in[4];
    const float* Wq = (const float*)d_in[5];
    const float* bq = (const float*)d_in[6];
    const float* kg = (const float*)d_in[7];
    const float* kb = (const float*)d_in[8];
    const float* Wk = (const float*)d_in[9];
    const float* bk = (const float*)d_in[10];
    float* out = (float*)d_out;

    if (!g_s2) {
        cudaStreamCreateWithFlags(&g_s2, cudaStreamNonBlocking);
        cudaEventCreateWithFlags(&g_evRoot, cudaEventDisableTiming);
        cudaEventCreateWithFlags(&g_evStats, cudaEventDisableTiming);
        cudaEventCreateWithFlags(&g_evDone, cudaEventDisableTiming);
        for (int c = 0; c < NCHUNK; c++)
            cudaEventCreateWithFlags(&g_evG[c], cudaEventDisableTiming);
    }

    // fork: stats on s2 runs concurrent with preps on stream 0
    cudaEventRecord(g_evRoot, 0);
    cudaStreamWaitEvent(g_s2, g_evRoot, 0);
    stats_kernel<<<ROWS / 8, 256, 0, g_s2>>>(x);
    cudaEventRecord(g_evStats, g_s2);

    prepA_kernel<<<dim3(4, 4), 256>>>(Wq, Wk);
    prepB_kernel<<<CDIM, 256>>>(Wq, Wk, bq, bk, kg, kb);
    prep2_kernel<<<1, 256>>>(bq, bk, kb);
    cudaStreamWaitEvent(0, g_evStats, 0);

    // pipelined chunks: gemm on stream 0 feeds attn on s2
    for (int c = 0; c < NCHUNK; c++) {
        gemm_kernel<<<dim3(2, BM_PER_CHUNK), 256>>>(x, qg, qb, c * BM_PER_CHUNK);
        cudaEventRecord(g_evG[c], 0);
        cudaStreamWaitEvent(g_s2, g_evG[c], 0);
        attn_kernel<<<ROWS_PER_CHUNK, 256, 0, g_s2>>>(y, z, out, c * ROWS_PER_CHUNK);
    }

    // join
    cudaEventRecord(g_evDone, g_s2);
    cudaStreamWaitEvent(0, g_evDone, 0);
}